// round 12
// baseline (speedup 1.0000x reference)
#include <cuda_runtime.h>
#include <cuda_bf16.h>
#include <stdint.h>

constexpr int B    = 4;
constexpr int H    = 8;
constexpr int LQ   = 1024;
constexpr int DH   = 64;
constexpr int KLEN = 1024;
constexpr int TBL  = 33;      // 2*MAX_REL_POS + 1
constexpr int SLAB = TBL * H; // 264 floats per (b,q)

// Scratch: P[bq][j][h]  (4096 * 264 floats = 4.3 MB)
__device__ float Pbuf[B * LQ * SLAB];

__device__ __forceinline__ void ffma2(unsigned long long& acc,
                                      unsigned long long a,
                                      unsigned long long b)
{
    asm("fma.rn.f32x2 %0, %1, %2, %0;" : "+l"(acc) : "l"(a), "l"(b));
}
__device__ __forceinline__ float f2lo(unsigned long long v) {
    return __uint_as_float((unsigned)v);
}
__device__ __forceinline__ float f2hi(unsigned long long v) {
    return __uint_as_float((unsigned)(v >> 32));
}

// ---------------------------------------------------------------------------
// Kernel 1: P[bq, j, h] = dot(query[b,h,q,:], table[j,:])
// One thread per row (b,qpos,h); q row in 64 regs (loaded once, coalesced-ish
// LDG.128). Table in smem, j-loop reads are warp-uniform broadcasts (1 wf per
// LDS.128). 64-thread blocks -> 512 blocks (all SMs). FOUR accumulator chains
// (depth 8, 32-cyc chain << 64-cyc FMA issue per j) + unroll 3 on j so loads
// pipeline under FMAs. FMA-pipe-bound target ~2.5-3.5 us.
// ---------------------------------------------------------------------------
__global__ __launch_bounds__(64)
void proj_kernel(const float* __restrict__ q,
                 const float* __restrict__ table)
{
    __shared__ __align__(16) ulonglong2 tsh[TBL * 16];  // 8.25 KB contiguous

    const int tid = threadIdx.x;

    // stage table: 528 x 16B, coalesced
    {
        const ulonglong2* t2 = reinterpret_cast<const ulonglong2*>(table);
        for (int i = tid; i < TBL * 16; i += 64) tsh[i] = t2[i];
    }

    const int r    = blockIdx.x * 64 + tid;   // 0 .. 32767
    const int h    = r & 7;
    const int bq   = r >> 3;
    const int qpos = bq & (LQ - 1);
    const int b    = bq >> 10;

    // q row -> 16 x ulonglong2 registers (once)
    ulonglong2 qv[16];
    {
        const ulonglong2* qr = reinterpret_cast<const ulonglong2*>(
            q + (((size_t)b * H + h) * LQ + qpos) * DH);
        #pragma unroll
        for (int c = 0; c < 16; c++) qv[c] = qr[c];
    }
    __syncthreads();

    float* pout = Pbuf + (size_t)bq * SLAB + h;

    #pragma unroll 3
    for (int j = 0; j < TBL; j++) {
        const ulonglong2* tr = &tsh[j * 16];
        unsigned long long a0 = 0ull, a1 = 0ull, a2 = 0ull, a3 = 0ull;
        #pragma unroll
        for (int c = 0; c < 16; c += 2) {
            ulonglong2 t0 = tr[c];
            ulonglong2 t1 = tr[c + 1];
            ffma2(a0, qv[c].x,     t0.x);
            ffma2(a1, qv[c].y,     t0.y);
            ffma2(a2, qv[c + 1].x, t1.x);
            ffma2(a3, qv[c + 1].y, t1.y);
        }
        float s = ((f2lo(a0) + f2hi(a0)) + (f2lo(a1) + f2hi(a1)))
                + ((f2lo(a2) + f2hi(a2)) + (f2lo(a3) + f2hi(a3)));
        pout[j * H] = s;
    }
}

// ---------------------------------------------------------------------------
// Kernel 2 (proven 22.8 us): out[b,h,q,k] = P[bq, idx(b,q,k), h]
// One block per (b,q). idx from int4 time_ids in registers. P slab staged in
// smem [j] -> 2 float4 (8 h). Gather 4 rows x 8 h into registers, then 8
// coalesced streaming STG.128.
// ---------------------------------------------------------------------------
__global__ __launch_bounds__(256)
void gather_kernel(const int* __restrict__ tids,
                   float* __restrict__ out)
{
    const int blk  = blockIdx.x;        // 0 .. B*LQ-1
    const int b    = blk >> 10;
    const int qpos = blk & (LQ - 1);
    const int tid  = threadIdx.x;

    __shared__ float4 st[TBL * 2];      // P slab, [j] -> 2 float4 (8 h values)

    if (tid < TBL * 2) {
        st[tid] = reinterpret_cast<const float4*>(
            Pbuf + (size_t)blk * SLAB)[tid];
    }

    const int tq = tids[b * KLEN + qpos];
    int4 t4 = reinterpret_cast<const int4*>(tids + (size_t)b * KLEN)[tid];

    int i0 = t4.x - tq; i0 = i0 < -16 ? -16 : (i0 > 16 ? 16 : i0); i0 += 16;
    int i1 = t4.y - tq; i1 = i1 < -16 ? -16 : (i1 > 16 ? 16 : i1); i1 += 16;
    int i2 = t4.z - tq; i2 = i2 < -16 ? -16 : (i2 > 16 ? 16 : i2); i2 += 16;
    int i3 = t4.w - tq; i3 = i3 < -16 ? -16 : (i3 > 16 ? 16 : i3); i3 += 16;

    __syncthreads();

    // gather 4 rows x 8 h into registers
    float r[4][8];
    {
        int ii[4] = {i0, i1, i2, i3};
        #pragma unroll
        for (int m = 0; m < 4; m++) {
            float4 a = st[2 * ii[m]];
            float4 c = st[2 * ii[m] + 1];
            r[m][0] = a.x; r[m][1] = a.y; r[m][2] = a.z; r[m][3] = a.w;
            r[m][4] = c.x; r[m][5] = c.y; r[m][6] = c.z; r[m][7] = c.w;
        }
    }

    // stream: for each h, one coalesced streaming float4 store
    #pragma unroll
    for (int h = 0; h < H; h++) {
        float4 v;
        v.x = r[0][h]; v.y = r[1][h]; v.z = r[2][h]; v.w = r[3][h];
        float4* o4 = reinterpret_cast<float4*>(
            out + ((((size_t)b * H + h) * LQ + qpos) * KLEN));
        __stcs(o4 + tid, v);
    }
}

extern "C" void kernel_launch(void* const* d_in, const int* in_sizes, int n_in,
                              void* d_out, int out_size)
{
    const float* q     = (const float*)d_in[0];
    const float* table = (const float*)d_in[1];
    const int*   tids  = (const int*)d_in[2];
    float*       out   = (float*)d_out;

    proj_kernel<<<(B * H * LQ) / 64, 64>>>(q, table);
    gather_kernel<<<B * LQ, 256>>>(tids, out);
}

// round 13
// speedup vs baseline: 1.0193x; 1.0193x over previous
#include <cuda_runtime.h>
#include <cuda_bf16.h>
#include <stdint.h>

constexpr int B    = 4;
constexpr int H    = 8;
constexpr int LQ   = 1024;
constexpr int DH   = 64;
constexpr int KLEN = 1024;
constexpr int TBL  = 33;      // 2*MAX_REL_POS + 1
constexpr int SLAB = TBL * H; // 264 floats per (b,q)

// Scratch: P[bq][j][h]  (4096 * 264 floats = 4.3 MB)
__device__ float Pbuf[B * LQ * SLAB];

__device__ __forceinline__ void ffma2(unsigned long long& acc,
                                      unsigned long long a,
                                      unsigned long long b)
{
    asm("fma.rn.f32x2 %0, %1, %2, %0;" : "+l"(acc) : "l"(a), "l"(b));
}
__device__ __forceinline__ float f2lo(unsigned long long v) {
    return __uint_as_float((unsigned)v);
}
__device__ __forceinline__ float f2hi(unsigned long long v) {
    return __uint_as_float((unsigned)(v >> 32));
}

// ---------------------------------------------------------------------------
// Kernel 1: P[bq, j, h] = dot(query[b,h,q,:], table[j,:])
// Block = (b, 8 consecutive qpos) -> 64 rows -> 8 COMPLETE output slabs.
//  * q staged with perfectly coalesced float4 LDG (8 contiguous 2KB chunks),
//    then each thread reads its own row ONCE into 16 packed-f32x2 registers.
//  * j-loop: table reads are warp-uniform broadcasts (1 wf), 4 FFMA2 chains.
//  * S accumulated in a smem slab, flushed with 528 coalesced float4 STG
//    (this kills the 33-scalar-scattered-store pattern of all prior projs).
// ---------------------------------------------------------------------------
__global__ __launch_bounds__(64)
void proj_kernel(const float* __restrict__ q,
                 const float* __restrict__ table)
{
    __shared__ __align__(16) ulonglong2 tsh[TBL * 16];  // 8.25 KB
    __shared__ __align__(16) float qsh[64 * 68];        // 17 KB (pad 68)
    __shared__ __align__(16) float ssh[8 * SLAB];       // 8.25 KB (8 slabs)

    const int tid = threadIdx.x;
    const int blk = blockIdx.x;          // 0..511
    const int b   = blk >> 7;            // 128 blocks per batch
    const int q0  = (blk & 127) * 8;     // first qpos

    // ---- stage table: 528 x 16B, coalesced ----
    {
        const ulonglong2* t2 = reinterpret_cast<const ulonglong2*>(table);
        for (int i = tid; i < TBL * 16; i += 64) tsh[i] = t2[i];
    }
    // ---- stage q: 8 chunks x 128 float4, each chunk contiguous ----
    for (int i = tid; i < 1024; i += 64) {
        int h = i >> 7;            // chunk = head
        int c = i & 127;           // float4 within chunk
        float4 v = reinterpret_cast<const float4*>(
            q + ((((size_t)b * H + h) * LQ) + q0) * DH)[c];
        int qp = c >> 4;           // row within chunk
        int cc = c & 15;
        *reinterpret_cast<float4*>(&qsh[(h * 8 + qp) * 68 + 4 * cc]) = v;
    }
    __syncthreads();

    // ---- own row -> registers (once; 4-way-conflict LDS, one-time) ----
    ulonglong2 qv[16];
    {
        const ulonglong2* myrow =
            reinterpret_cast<const ulonglong2*>(&qsh[tid * 68]);
        #pragma unroll
        for (int c = 0; c < 16; c++) qv[c] = myrow[c];
    }

    const int h  = tid >> 3;    // 0..7
    const int qp = tid & 7;     // 0..7
    float* sout = &ssh[qp * SLAB + h];    // + j*H per j

    #pragma unroll 3
    for (int j = 0; j < TBL; j++) {
        const ulonglong2* tr = &tsh[j * 16];   // warp-uniform broadcast
        unsigned long long a0 = 0ull, a1 = 0ull, a2 = 0ull, a3 = 0ull;
        #pragma unroll
        for (int c = 0; c < 16; c += 2) {
            ulonglong2 t0 = tr[c];
            ulonglong2 t1 = tr[c + 1];
            ffma2(a0, qv[c].x,     t0.x);
            ffma2(a1, qv[c].y,     t0.y);
            ffma2(a2, qv[c + 1].x, t1.x);
            ffma2(a3, qv[c + 1].y, t1.y);
        }
        sout[j * H] = ((f2lo(a0) + f2hi(a0)) + (f2lo(a1) + f2hi(a1)))
                    + ((f2lo(a2) + f2hi(a2)) + (f2lo(a3) + f2hi(a3)));
    }
    __syncthreads();

    // ---- flush 8 slabs (2112 floats = 528 float4), fully coalesced ----
    {
        float4* dst = reinterpret_cast<float4*>(
            Pbuf + ((size_t)b * LQ + q0) * SLAB);
        const float4* src = reinterpret_cast<const float4*>(ssh);
        for (int i = tid; i < 528; i += 64) dst[i] = src[i];
    }
}

// ---------------------------------------------------------------------------
// Kernel 2 (proven ~22.8 us, unchanged): out[b,h,q,k] = P[bq, idx(b,q,k), h]
// ---------------------------------------------------------------------------
__global__ __launch_bounds__(256)
void gather_kernel(const int* __restrict__ tids,
                   float* __restrict__ out)
{
    const int blk  = blockIdx.x;        // 0 .. B*LQ-1
    const int b    = blk >> 10;
    const int qpos = blk & (LQ - 1);
    const int tid  = threadIdx.x;

    __shared__ float4 st[TBL * 2];      // P slab, [j] -> 2 float4 (8 h values)

    if (tid < TBL * 2) {
        st[tid] = reinterpret_cast<const float4*>(
            Pbuf + (size_t)blk * SLAB)[tid];
    }

    const int tq = tids[b * KLEN + qpos];
    int4 t4 = reinterpret_cast<const int4*>(tids + (size_t)b * KLEN)[tid];

    int i0 = t4.x - tq; i0 = i0 < -16 ? -16 : (i0 > 16 ? 16 : i0); i0 += 16;
    int i1 = t4.y - tq; i1 = i1 < -16 ? -16 : (i1 > 16 ? 16 : i1); i1 += 16;
    int i2 = t4.z - tq; i2 = i2 < -16 ? -16 : (i2 > 16 ? 16 : i2); i2 += 16;
    int i3 = t4.w - tq; i3 = i3 < -16 ? -16 : (i3 > 16 ? 16 : i3); i3 += 16;

    __syncthreads();

    float r[4][8];
    {
        int ii[4] = {i0, i1, i2, i3};
        #pragma unroll
        for (int m = 0; m < 4; m++) {
            float4 a = st[2 * ii[m]];
            float4 c = st[2 * ii[m] + 1];
            r[m][0] = a.x; r[m][1] = a.y; r[m][2] = a.z; r[m][3] = a.w;
            r[m][4] = c.x; r[m][5] = c.y; r[m][6] = c.z; r[m][7] = c.w;
        }
    }

    #pragma unroll
    for (int h = 0; h < H; h++) {
        float4 v;
        v.x = r[0][h]; v.y = r[1][h]; v.z = r[2][h]; v.w = r[3][h];
        float4* o4 = reinterpret_cast<float4*>(
            out + ((((size_t)b * H + h) * LQ + qpos) * KLEN));
        __stcs(o4 + tid, v);
    }
}

extern "C" void kernel_launch(void* const* d_in, const int* in_sizes, int n_in,
                              void* d_out, int out_size)
{
    const float* q     = (const float*)d_in[0];
    const float* table = (const float*)d_in[1];
    const int*   tids  = (const int*)d_in[2];
    float*       out   = (float*)d_out;

    proj_kernel<<<512, 64>>>(q, table);
    gather_kernel<<<B * LQ, 256>>>(tids, out);
}